// round 8
// baseline (speedup 1.0000x reference)
#include <cuda_runtime.h>
#include <cuda_bf16.h>
#include <cstdint>
#include <math.h>

#define B_ROWS 2048
#define N_TOT  4096
#define DIM    256
#define SCALE  2.0f        // 1/TEMPERATURE
#define TM 128
#define TN 128
#define KC 64
#define NKC (DIM / KC)
#define PAD_BF16 8
#define ROWB ((KC + PAD_BF16) * 2)       // 144 B smem row stride
#define ABUF_B (TM * ROWB)
#define BBUF_B (TN * ROWB)
#define SMEM_DYN (2 * (ABUF_B + BBUF_B)) // 73728
#define NTILE (N_TOT / TM)               // 32
#define NBLK  (NTILE * (NTILE + 1) / 2)  // 528 triangular tiles
#define NTHR  512

__device__ __nv_bfloat16 g_zb[N_TOT * DIM];
__device__ float g_rowsum[N_TOT];
__device__ float g_pos[N_TOT];
__device__ unsigned int g_count;

// ---------------------------------------------------------------- helpers ---
__device__ __forceinline__ uint32_t smem_u32(const void* p) {
    uint32_t a;
    asm("{ .reg .u64 t; cvta.to.shared.u64 t, %1; cvt.u32.u64 %0, t; }" : "=r"(a) : "l"(p));
    return a;
}
__device__ __forceinline__ void cp_async16(uint32_t dst, const void* src) {
    asm volatile("cp.async.cg.shared.global [%0], [%1], 16;" :: "r"(dst), "l"(src));
}
__device__ __forceinline__ void cp_commit() { asm volatile("cp.async.commit_group;"); }
template <int N>
__device__ __forceinline__ void cp_wait() {
    asm volatile("cp.async.wait_group %0;" :: "n"(N));
}
__device__ __forceinline__ void ldmatrix4(uint32_t* r, uint32_t addr) {
    asm volatile("ldmatrix.sync.aligned.m8n8.x4.shared.b16 {%0,%1,%2,%3}, [%4];"
                 : "=r"(r[0]), "=r"(r[1]), "=r"(r[2]), "=r"(r[3]) : "r"(addr));
}
__device__ __forceinline__ void mma16816(float* c, const uint32_t* a, uint32_t b0, uint32_t b1) {
    asm volatile(
        "mma.sync.aligned.m16n8k16.row.col.f32.bf16.bf16.f32 "
        "{%0,%1,%2,%3}, {%4,%5,%6,%7}, {%8,%9}, {%0,%1,%2,%3};"
        : "+f"(c[0]), "+f"(c[1]), "+f"(c[2]), "+f"(c[3])
        : "r"(a[0]), "r"(a[1]), "r"(a[2]), "r"(a[3]), "r"(b0), "r"(b1));
}

// ------------------------------------------------------- normalize (bf16) ---
__global__ __launch_bounds__(256) void normalize_kernel(const float* __restrict__ zi,
                                                        const float* __restrict__ zj) {
    const int warp = (blockIdx.x * 256 + threadIdx.x) >> 5;
    const int lane = threadIdx.x & 31;
    const int l    = lane & 15;
    const int row  = warp * 2 + (lane >> 4);   // 2048 warps x 2 rows = 4096
    const float* src = (row < B_ROWS) ? zi + (size_t)row * DIM
                                      : zj + (size_t)(row - B_ROWS) * DIM;
    float4 v[4];
    #pragma unroll
    for (int t = 0; t < 4; t++) v[t] = ((const float4*)src)[l * 4 + t];

    float ss = 0.0f;
    #pragma unroll
    for (int t = 0; t < 4; t++)
        ss += v[t].x*v[t].x + v[t].y*v[t].y + v[t].z*v[t].z + v[t].w*v[t].w;
    #pragma unroll
    for (int m = 8; m; m >>= 1) ss += __shfl_xor_sync(0xffffffffu, ss, m);
    const float inv = 1.0f / fmaxf(sqrtf(ss), 1e-12f);

    __nv_bfloat16 o[16];
    #pragma unroll
    for (int t = 0; t < 4; t++) {
        o[t*4+0] = __float2bfloat16(v[t].x * inv);
        o[t*4+1] = __float2bfloat16(v[t].y * inv);
        o[t*4+2] = __float2bfloat16(v[t].z * inv);
        o[t*4+3] = __float2bfloat16(v[t].w * inv);
    }
    uint4* dst = (uint4*)(g_zb + (size_t)row * DIM + l * 16);
    dst[0] = ((const uint4*)o)[0];
    dst[1] = ((const uint4*)o)[1];

    if (l == 0) g_rowsum[row] = 0.0f;
    if (blockIdx.x == 0 && threadIdx.x == 0) g_count = 0u;
}

// ------- fused sim: HMMA, triangular tiles, 16 warps (32x32 warp tile) ------
extern __shared__ char dsm[];

__global__ __launch_bounds__(NTHR, 2) void sim_mma_kernel(float* __restrict__ out) {
    __shared__ float s_row[TM];
    __shared__ float s_col[TN];
    __shared__ int   s_last;

    const int tid  = threadIdx.x;
    const int wid  = tid >> 5;
    const int lane = tid & 31;
    const int wm   = wid & 3;     // 0..3 : 32-row slab
    const int wn   = wid >> 2;    // 0..3 : 32-col slab

    // triangular decode: bi <= bj
    int t = blockIdx.x, bi = 0;
    while (t >= NTILE - bi) { t -= NTILE - bi; bi++; }
    const int bj   = bi + t;
    const bool diag = (bi == bj);
    const int i0 = bi * TM;
    const int j0 = bj * TN;

    const uint32_t base = smem_u32(dsm);
    uint32_t Ab[2] = { base,          base + ABUF_B + BBUF_B };
    uint32_t Bb[2] = { base + ABUF_B, base + ABUF_B + BBUF_B + ABUF_B };
    if (diag) { Bb[0] = Ab[0]; Bb[1] = Ab[1]; }   // A tile == B tile

    auto prefetch = [&](int kc, int b) {
        const __nv_bfloat16* gA = g_zb + (size_t)i0 * DIM + kc * KC;
        #pragma unroll
        for (int it = 0; it < 2; it++) {           // 1024 ops / 512 thr
            int idx = it * NTHR + tid;
            int row = idx >> 3, c8 = idx & 7;
            cp_async16(Ab[b] + row * ROWB + c8 * 16, gA + (size_t)row * DIM + c8 * 8);
        }
        if (!diag) {
            const __nv_bfloat16* gB = g_zb + (size_t)j0 * DIM + kc * KC;
            #pragma unroll
            for (int it = 0; it < 2; it++) {
                int idx = it * NTHR + tid;
                int row = idx >> 3, c8 = idx & 7;
                cp_async16(Bb[b] + row * ROWB + c8 * 16, gB + (size_t)row * DIM + c8 * 8);
            }
        }
        cp_commit();
    };

    float c[2][4][4] = {};   // [mt][nt][e], 32 accums
    prefetch(0, 0);

    for (int kc = 0; kc < NKC; kc++) {
        if (kc + 1 < NKC) prefetch(kc + 1, (kc + 1) & 1);
        if (kc + 1 < NKC) cp_wait<1>(); else cp_wait<0>();
        __syncthreads();

        const uint32_t A = Ab[kc & 1];
        const uint32_t B = Bb[kc & 1];
        const int lr = lane & 15, lh = lane >> 4;

        #pragma unroll
        for (int ks = 0; ks < KC / 16; ks++) {
            const uint32_t koff = ks * 32 + lh * 16;
            uint32_t af[2][4], bf[2][4];
            #pragma unroll
            for (int mt = 0; mt < 2; mt++)
                ldmatrix4(af[mt], A + (wm * 32 + mt * 16 + lr) * ROWB + koff);
            #pragma unroll
            for (int n2 = 0; n2 < 2; n2++)
                ldmatrix4(bf[n2], B + (wn * 32 + n2 * 16 + lr) * ROWB + koff);
            #pragma unroll
            for (int mt = 0; mt < 2; mt++)
                #pragma unroll
                for (int nt = 0; nt < 4; nt++)
                    mma16816(c[mt][nt], af[mt], bf[nt >> 1][nt & 1], bf[nt >> 1][(nt & 1) + 2]);
        }
        __syncthreads();
    }

    // ---- epilogue: exp once; row sums (i) + mirrored col sums (j) ----------
    if (tid < TM) { s_row[tid] = 0.0f; s_col[tid] = 0.0f; }
    __syncthreads();

    const int grp = lane >> 2, tig = lane & 3;
    float rs[4] = {}, cs[8] = {};

    #pragma unroll
    for (int mt = 0; mt < 2; mt++) {
        #pragma unroll
        for (int rh = 0; rh < 2; rh++) {
            const int i    = i0 + wm * 32 + mt * 16 + grp + rh * 8;
            const int posj = (i + B_ROWS) & (N_TOT - 1);
            #pragma unroll
            for (int nt = 0; nt < 4; nt++) {
                #pragma unroll
                for (int cb = 0; cb < 2; cb++) {
                    const int j   = j0 + wn * 32 + nt * 8 + tig * 2 + cb;
                    const float s = SCALE * c[mt][nt][rh * 2 + cb];
                    const float e = __expf(s);
                    if (!diag) {
                        rs[mt * 2 + rh] += e;
                        cs[nt * 2 + cb] += e;
                        if (j == posj) { g_pos[i] = s; g_pos[j] = s; }
                    } else if (j != i) {
                        rs[mt * 2 + rh] += e;
                    }
                }
            }
        }
    }
    // row sums: reduce across tig (lane bits 0-1)
    #pragma unroll
    for (int r = 0; r < 4; r++) {
        rs[r] += __shfl_xor_sync(0xffffffffu, rs[r], 1);
        rs[r] += __shfl_xor_sync(0xffffffffu, rs[r], 2);
    }
    if (tig == 0) {
        #pragma unroll
        for (int r = 0; r < 4; r++)
            atomicAdd(&s_row[wm * 32 + (r >> 1) * 16 + grp + (r & 1) * 8], rs[r]);
    }
    // col sums: reduce across grp (lane bits 2-4)
    if (!diag) {
        #pragma unroll
        for (int r = 0; r < 8; r++) {
            cs[r] += __shfl_xor_sync(0xffffffffu, cs[r], 4);
            cs[r] += __shfl_xor_sync(0xffffffffu, cs[r], 8);
            cs[r] += __shfl_xor_sync(0xffffffffu, cs[r], 16);
        }
        if (grp == 0) {
            #pragma unroll
            for (int r = 0; r < 8; r++)
                atomicAdd(&s_col[wn * 32 + (r >> 1) * 8 + tig * 2 + (r & 1)], cs[r]);
        }
    }
    __syncthreads();
    if (tid < TM) {
        atomicAdd(&g_rowsum[i0 + tid], s_row[tid]);
        if (!diag) atomicAdd(&g_rowsum[j0 + tid], s_col[tid]);
    }

    // ---- last CTA computes the loss ----------------------------------------
    __threadfence();
    if (tid == 0) s_last = (atomicAdd(&g_count, 1u) == (unsigned)(gridDim.x - 1));
    __syncthreads();
    if (s_last) {
        float sum = 0.0f;
        for (int i = tid; i < N_TOT; i += NTHR)
            sum += logf(__ldcg(&g_rowsum[i])) - __ldcg(&g_pos[i]);
        #pragma unroll
        for (int m = 16; m; m >>= 1) sum += __shfl_xor_sync(0xffffffffu, sum, m);
        __shared__ float sh[16];
        if (lane == 0) sh[wid] = sum;
        __syncthreads();
        if (tid < 32) {
            float v = (tid < 16) ? sh[tid] : 0.0f;
            #pragma unroll
            for (int m = 8; m; m >>= 1) v += __shfl_xor_sync(0xffffffffu, v, m);
            if (tid == 0) out[0] = v * (1.0f / N_TOT);
        }
    }
}

// ---------------------------------------------------------------------------
extern "C" void kernel_launch(void* const* d_in, const int* in_sizes, int n_in,
                              void* d_out, int out_size) {
    const float* zi = (const float*)d_in[0];
    const float* zj = (const float*)d_in[1];
    float* out = (float*)d_out;

    cudaFuncSetAttribute(sim_mma_kernel,
                         cudaFuncAttributeMaxDynamicSharedMemorySize, SMEM_DYN);

    normalize_kernel<<<N_TOT / 16, 256>>>(zi, zj);
    sim_mma_kernel<<<NBLK, NTHR, SMEM_DYN>>>(out);
}